// round 13
// baseline (speedup 1.0000x reference)
#include <cuda_runtime.h>
#include <cuda_fp16.h>
#include <math.h>
#include <stdint.h>

// Shape (fixed): B=8, L=2048, E=8, D=512
#define NTOK   16384
#define NE     8
#define ND     512
#define NROWS  (NTOK * NE)          // 131072

// ---------------- device scratch (allocs forbidden; __device__ globals OK) --
__device__ __half g_Xh[(size_t)NROWS * ND];    // 128 MB (fp16 X)
__device__ __half g_Wnh[ND * ND];
__device__ __half g_Wsh[ND * ND];
__device__ float  g_S[(size_t)NTOK * NE * NE]; // 4 MB per-token 8x8 strength
__device__ float  g_bias[ND];

__device__ __forceinline__ float sigmoidf_(float z) { return 1.0f / (1.0f + __expf(-z)); }
__device__ __forceinline__ float gelu_exact(float z) {
    return 0.5f * z * (1.0f + erff(z * 0.70710678118654752f));
}
__device__ __forceinline__ uint32_t smem_u32(const void* p) {
    uint32_t a;
    asm("{ .reg .u64 t; cvta.to.shared.u64 t, %1; cvt.u32.u64 %0, t; }" : "=r"(a) : "l"(p));
    return a;
}
__device__ __forceinline__ void cp16(uint32_t dst, const void* src) {
    asm volatile("cp.async.cg.shared.global [%0], [%1], 16;" :: "r"(dst), "l"(src));
}
__device__ __forceinline__ void ldm_x4(uint32_t* r, uint32_t addr) {
    asm volatile("ldmatrix.sync.aligned.m8n8.x4.shared.b16 {%0,%1,%2,%3}, [%4];"
                 : "=r"(r[0]), "=r"(r[1]), "=r"(r[2]), "=r"(r[3]) : "r"(addr));
}
__device__ __forceinline__ void mma16816(float* c, const uint32_t* a, const uint32_t* b) {
    asm volatile(
        "mma.sync.aligned.m16n8k16.row.col.f32.f16.f16.f32 "
        "{%0,%1,%2,%3}, {%4,%5,%6,%7}, {%8,%9}, {%0,%1,%2,%3};"
        : "+f"(c[0]), "+f"(c[1]), "+f"(c[2]), "+f"(c[3])
        : "r"(a[0]), "r"(a[1]), "r"(a[2]), "r"(a[3]), "r"(b[0]), "r"(b[1]));
}

// ---------------------------------------------------------------------------
// Prep 1: per-token strength matrix + X -> fp16.
// ---------------------------------------------------------------------------
__global__ __launch_bounds__(256) void prep_token_kernel(
    const float* __restrict__ x, const float* __restrict__ w_msg,
    const float* __restrict__ b_msg, const float* __restrict__ adjL)
{
    __shared__ float sx[NE * ND];
    __shared__ float swm[2 * ND];
    __shared__ float sa[NE], sb[NE];

    const int tid = threadIdx.x;
    const int token = blockIdx.x;

    const float4* xin = reinterpret_cast<const float4*>(x + (size_t)token * (NE * ND));
    float4* sx4 = reinterpret_cast<float4*>(sx);
    #pragma unroll 4
    for (int i = tid; i < NE * ND / 4; i += 256) sx4[i] = xin[i];
    const float4* wm4 = reinterpret_cast<const float4*>(w_msg);
    float4* swm4 = reinterpret_cast<float4*>(swm);
    for (int i = tid; i < 2 * ND / 4; i += 256) swm4[i] = wm4[i];
    __syncthreads();

    {
        const int warp = tid >> 5, lane = tid & 31;
        float pa = 0.f, pb = 0.f;
        #pragma unroll
        for (int d = lane; d < ND; d += 32) {
            float xv = sx[warp * ND + d];
            pa += xv * swm[d];
            pb += xv * swm[ND + d];
        }
        #pragma unroll
        for (int off = 16; off; off >>= 1) {
            pa += __shfl_xor_sync(0xffffffff, pa, off);
            pb += __shfl_xor_sync(0xffffffff, pb, off);
        }
        if (lane == 0) { sa[warp] = pa; sb[warp] = pb; }
    }
    __syncthreads();

    if (tid < NE * NE) {
        const int i = tid >> 3, j = tid & 7;
        float v = 0.f;
        if (i != j)
            v = sigmoidf_(adjL[tid]) * sigmoidf_(sa[i] + sb[j] + b_msg[0]);
        g_S[(size_t)token * 64 + tid] = v;
    }

    const size_t base = (size_t)token * (NE * ND);
    #pragma unroll 4
    for (int i = tid; i < NE * ND / 4; i += 256) {
        float4 v = sx4[i];
        __half2 h0 = __floats2half2_rn(v.x, v.y);
        __half2 h1 = __floats2half2_rn(v.z, v.w);
        uint2 uh;
        uh.x = *reinterpret_cast<uint32_t*>(&h0);
        uh.y = *reinterpret_cast<uint32_t*>(&h1);
        *reinterpret_cast<uint2*>(g_Xh + base + (size_t)i * 4) = uh;
    }
}

__global__ __launch_bounds__(256) void prep_weight_kernel(
    const float* __restrict__ Wn, const float* __restrict__ bn,
    const float* __restrict__ Ws, const float* __restrict__ bs)
{
    const int idx = blockIdx.x * 256 + threadIdx.x;
    if (idx < ND * ND) {
        g_Wnh[idx] = __float2half_rn(Wn[idx]);
        g_Wsh[idx] = __float2half_rn(Ws[idx]);
    }
    if (idx < ND) g_bias[idx] = bn[idx] + bs[idx];
}

// ---------------------------------------------------------------------------
// fp16 HMMA GEMM: per CTA rows 128 (16 tokens x 8 experts), cols 128, K=512.
// P = X@Wn^T and S = X@Ws^T, single fp16 pass each (fp32 accum).
// Warp grid 4m x 2n; each warp: 32 rows x 64 cols per output (acc = 128 regs).
// One barrier per K-chunk; B fragments via packed ldmatrix.x4.
// Epilogue in two 64-col halves: out = gelu( per-token 8x8 mix of P + S + b ).
// ---------------------------------------------------------------------------
#define BKC      64                       // k per chunk
#define NCHUNKS  (ND / BKC)               // 8
#define APAD_B   144                      // row stride bytes (128B data + 16 pad)
#define A_BYTES  (128 * APAD_B)           // 18432
#define W_BYTES  (128 * APAD_B)           // 18432 per weight matrix
#define STG_B    (A_BYTES + 2 * W_BYTES)  // 55296
#define SM_STAGE 4864                     // after sbias(512) + ssmat(4096) + pad
#define SMEM_TOTAL (SM_STAGE + 2 * STG_B) // 115456  (1 CTA/SM)
#define EPS_STRIDE 66

__global__ __launch_bounds__(256, 1) void gemm_hmma_kernel(float* __restrict__ out)
{
    extern __shared__ char sm[];
    const int tid = threadIdx.x;
    const int wid = tid >> 5, lane = tid & 31;
    const int warpM = wid & 3, warpN = wid >> 2;      // 4 x 2 warp grid

    const int ntile = blockIdx.x;        // 0..3
    const int mtile = blockIdx.y;        // 0..1023
    const int colBase = ntile * 128;
    const int rowBase = mtile * 128;
    const int tokBase = mtile * 16;

    float* sbias = reinterpret_cast<float*>(sm);
    float* ssmat = reinterpret_cast<float*>(sm + 512);
    if (tid < 128) sbias[tid] = g_bias[colBase + tid];
    for (int i = tid; i < 1024; i += 256) ssmat[i] = g_S[(size_t)tokBase * 64 + i];

    const uint32_t stage0 = smem_u32(sm) + SM_STAGE;
    const __half* Ah = g_Xh  + (size_t)rowBase * ND;
    const __half* Bn = g_Wnh + (size_t)colBase * ND;
    const __half* Bs = g_Wsh + (size_t)colBase * ND;

    // ---- async chunk loader: 12 x 16B per thread per chunk ----
    auto issue_chunk = [&](int c) {
        const uint32_t sb = stage0 + (c & 1) * STG_B;
        const int koff = c * BKC;
        #pragma unroll
        for (int i = 0; i < 4; i++) {                 // A: 1024 cp16
            const int q = tid + i * 256;
            const int row = q >> 3, seg = q & 7;
            cp16(sb + row * APAD_B + seg * 16,
                 Ah + (size_t)row * ND + koff + seg * 8);
        }
        #pragma unroll
        for (int i = 0; i < 4; i++) {                 // Wn, Ws: 1024 cp16 each
            const int q = tid + i * 256;
            const int row = q >> 3, seg = q & 7;
            const uint32_t d = row * APAD_B + seg * 16;
            const size_t g = (size_t)row * ND + koff + seg * 8;
            cp16(sb + A_BYTES + d,           Bn + g);
            cp16(sb + A_BYTES + W_BYTES + d, Bs + g);
        }
    };

    float accP[2][8][4], accS[2][8][4];
    #pragma unroll
    for (int mt = 0; mt < 2; mt++)
        #pragma unroll
        for (int nt = 0; nt < 8; nt++)
            #pragma unroll
            for (int u = 0; u < 4; u++) { accP[mt][nt][u] = 0.f; accS[mt][nt][u] = 0.f; }

    issue_chunk(0);
    asm volatile("cp.async.commit_group;" ::: "memory");

    // ---- ldmatrix lane addressing ----
    // A (x4, one 16x16 m-tile): lanes 0-15 rows, 16-31 rows col+8
    const int a_row = ((lane >> 3) & 1) * 8 + (lane & 7);
    const int a_col = (lane >> 4) * 8;
    // B packed x4: matrix m = lane>>3 covers (tile m>>1, k-half m&1)
    const int bm = lane >> 3, br = lane & 7;
    const uint32_t b_lane_off =
        (uint32_t)((warpN * 64 + (bm >> 1) * 8 + br) * APAD_B + (bm & 1) * 16);

    #pragma unroll 1
    for (int c = 0; c < NCHUNKS; c++) {
        asm volatile("cp.async.wait_group 0;" ::: "memory");
        __syncthreads();
        if (c + 1 < NCHUNKS) {
            issue_chunk(c + 1);
            asm volatile("cp.async.commit_group;" ::: "memory");
        }

        const uint32_t sb = stage0 + (c & 1) * STG_B;
        #pragma unroll
        for (int ks = 0; ks < 4; ks++) {
            const int k0 = ks * 16;
            uint32_t af[2][4];
            #pragma unroll
            for (int mt = 0; mt < 2; mt++) {
                const uint32_t ra = sb +
                    (warpM * 32 + mt * 16 + a_row) * APAD_B + (k0 + a_col) * 2;
                ldm_x4(af[mt], ra);
            }
            #pragma unroll
            for (int ntp = 0; ntp < 4; ntp++) {       // pair of n8 tiles per x4
                const uint32_t bo = sb + A_BYTES + b_lane_off +
                    (uint32_t)(ntp * 16 * APAD_B) + k0 * 2;
                uint32_t bn4[4], bs4[4];
                ldm_x4(bn4, bo);
                ldm_x4(bs4, bo + W_BYTES);
                #pragma unroll
                for (int sub = 0; sub < 2; sub++) {
                    const int nt = ntp * 2 + sub;
                    #pragma unroll
                    for (int mt = 0; mt < 2; mt++) {
                        mma16816(accP[mt][nt], af[mt], &bn4[sub * 2]);
                        mma16816(accS[mt][nt], af[mt], &bs4[sub * 2]);
                    }
                }
            }
        }
    }

    // ---- epilogue: two 64-col halves (half h written by warpN==h warps) ----
    float* sP = reinterpret_cast<float*>(sm + SM_STAGE);
    float* sS = sP + 128 * EPS_STRIDE;
    const int rr = lane >> 2;
    const int cc = 2 * (lane & 3);

    #pragma unroll
    for (int h = 0; h < 2; h++) {
        __syncthreads();
        if (warpN == h) {
            #pragma unroll
            for (int mt = 0; mt < 2; mt++) {
                #pragma unroll
                for (int nt = 0; nt < 8; nt++) {
                    const int r0 = warpM * 32 + mt * 16 + rr;
                    const int c0 = nt * 8 + cc;            // 0..63 within half
                    sP[r0 * EPS_STRIDE + c0]           = accP[mt][nt][0];
                    sP[r0 * EPS_STRIDE + c0 + 1]       = accP[mt][nt][1];
                    sP[(r0 + 8) * EPS_STRIDE + c0]     = accP[mt][nt][2];
                    sP[(r0 + 8) * EPS_STRIDE + c0 + 1] = accP[mt][nt][3];
                    sS[r0 * EPS_STRIDE + c0]           = accS[mt][nt][0];
                    sS[r0 * EPS_STRIDE + c0 + 1]       = accS[mt][nt][1];
                    sS[(r0 + 8) * EPS_STRIDE + c0]     = accS[mt][nt][2];
                    sS[(r0 + 8) * EPS_STRIDE + c0 + 1] = accS[mt][nt][3];
                }
            }
        }
        __syncthreads();

        {
            const int r = tid >> 1;              // local row 0..127
            const int cg = (tid & 1) * 32;       // col half within the 64
            const int tt = r >> 3, ei = r & 7;
            float sreg[8];
            #pragma unroll
            for (int j = 0; j < 8; j++) sreg[j] = ssmat[tt * 64 + ei * 8 + j];

            float* outrow = out + (size_t)(rowBase + r) * ND + colBase + h * 64 + cg;
            #pragma unroll
            for (int q = 0; q < 8; q++) {        // 8 x float4
                float4 o;
                #pragma unroll
                for (int u = 0; u < 4; u++) {
                    const int ccol = cg + q * 4 + u;
                    float mix = 0.f;
                    #pragma unroll
                    for (int j = 0; j < 8; j++)
                        mix = fmaf(sreg[j], sP[(tt * 8 + j) * EPS_STRIDE + ccol], mix);
                    const float val = mix + sS[r * EPS_STRIDE + ccol]
                                    + sbias[h * 64 + ccol];
                    (&o.x)[u] = gelu_exact(val);
                }
                *reinterpret_cast<float4*>(outrow + q * 4) = o;
            }
        }
    }
}

// ---------------------------------------------------------------------------
extern "C" void kernel_launch(void* const* d_in, const int* in_sizes, int n_in,
                              void* d_out, int out_size)
{
    const float* x     = (const float*)d_in[0];
    const float* Wn    = (const float*)d_in[1];
    const float* bn    = (const float*)d_in[2];
    const float* Ws    = (const float*)d_in[3];
    const float* bs    = (const float*)d_in[4];
    const float* w_msg = (const float*)d_in[5];
    const float* b_msg = (const float*)d_in[6];
    const float* adjL  = (const float*)d_in[7];
    float* out = (float*)d_out;

    static bool attr_done = false;
    if (!attr_done) {
        cudaFuncSetAttribute(gemm_hmma_kernel,
                             cudaFuncAttributeMaxDynamicSharedMemorySize, SMEM_TOTAL);
        attr_done = true;
    }

    prep_token_kernel<<<NTOK, 256>>>(x, w_msg, b_msg, adjL);
    prep_weight_kernel<<<(ND * ND + 255) / 256, 256>>>(Wn, bn, Ws, bs);

    dim3 grid(ND / 128, NROWS / 128);    // (4, 1024)
    gemm_hmma_kernel<<<grid, 256, SMEM_TOTAL>>>(out);
}

// round 15
// speedup vs baseline: 1.1451x; 1.1451x over previous
#include <cuda_runtime.h>
#include <cuda_fp16.h>
#include <math.h>
#include <stdint.h>

// Shape (fixed): B=8, L=2048, E=8, D=512
#define NTOK   16384
#define NE     8
#define ND     512
#define NROWS  (NTOK * NE)          // 131072

// ---------------- device scratch (allocs forbidden; __device__ globals OK) --
__device__ __half g_Xh[(size_t)NROWS * ND];    // 128 MB (fp16 X)
__device__ __half g_Wnh[ND * ND];
__device__ __half g_Wsh[ND * ND];
__device__ float  g_S[(size_t)NTOK * NE * NE]; // 4 MB per-token 8x8 strength
__device__ float  g_bias[ND];

__device__ __forceinline__ float sigmoidf_(float z) { return 1.0f / (1.0f + __expf(-z)); }
__device__ __forceinline__ float gelu_exact(float z) {
    return 0.5f * z * (1.0f + erff(z * 0.70710678118654752f));
}
__device__ __forceinline__ uint32_t smem_u32(const void* p) {
    uint32_t a;
    asm("{ .reg .u64 t; cvta.to.shared.u64 t, %1; cvt.u32.u64 %0, t; }" : "=r"(a) : "l"(p));
    return a;
}
__device__ __forceinline__ void cp16(uint32_t dst, const void* src) {
    asm volatile("cp.async.cg.shared.global [%0], [%1], 16;" :: "r"(dst), "l"(src));
}
__device__ __forceinline__ void ldm_x4(uint32_t* r, uint32_t addr) {
    asm volatile("ldmatrix.sync.aligned.m8n8.x4.shared.b16 {%0,%1,%2,%3}, [%4];"
                 : "=r"(r[0]), "=r"(r[1]), "=r"(r[2]), "=r"(r[3]) : "r"(addr));
}
__device__ __forceinline__ void mma16816(float* c, const uint32_t* a, const uint32_t* b) {
    asm volatile(
        "mma.sync.aligned.m16n8k16.row.col.f32.f16.f16.f32 "
        "{%0,%1,%2,%3}, {%4,%5,%6,%7}, {%8,%9}, {%0,%1,%2,%3};"
        : "+f"(c[0]), "+f"(c[1]), "+f"(c[2]), "+f"(c[3])
        : "r"(a[0]), "r"(a[1]), "r"(a[2]), "r"(a[3]), "r"(b[0]), "r"(b[1]));
}

// ---------------------------------------------------------------------------
// Prep 1: per-token strength matrix + X -> fp16.   (unchanged from R11)
// ---------------------------------------------------------------------------
__global__ __launch_bounds__(256) void prep_token_kernel(
    const float* __restrict__ x, const float* __restrict__ w_msg,
    const float* __restrict__ b_msg, const float* __restrict__ adjL)
{
    __shared__ float sx[NE * ND];
    __shared__ float swm[2 * ND];
    __shared__ float sa[NE], sb[NE];

    const int tid = threadIdx.x;
    const int token = blockIdx.x;

    const float4* xin = reinterpret_cast<const float4*>(x + (size_t)token * (NE * ND));
    float4* sx4 = reinterpret_cast<float4*>(sx);
    #pragma unroll 4
    for (int i = tid; i < NE * ND / 4; i += 256) sx4[i] = xin[i];
    const float4* wm4 = reinterpret_cast<const float4*>(w_msg);
    float4* swm4 = reinterpret_cast<float4*>(swm);
    for (int i = tid; i < 2 * ND / 4; i += 256) swm4[i] = wm4[i];
    __syncthreads();

    {
        const int warp = tid >> 5, lane = tid & 31;
        float pa = 0.f, pb = 0.f;
        #pragma unroll
        for (int d = lane; d < ND; d += 32) {
            float xv = sx[warp * ND + d];
            pa += xv * swm[d];
            pb += xv * swm[ND + d];
        }
        #pragma unroll
        for (int off = 16; off; off >>= 1) {
            pa += __shfl_xor_sync(0xffffffff, pa, off);
            pb += __shfl_xor_sync(0xffffffff, pb, off);
        }
        if (lane == 0) { sa[warp] = pa; sb[warp] = pb; }
    }
    __syncthreads();

    if (tid < NE * NE) {
        const int i = tid >> 3, j = tid & 7;
        float v = 0.f;
        if (i != j)
            v = sigmoidf_(adjL[tid]) * sigmoidf_(sa[i] + sb[j] + b_msg[0]);
        g_S[(size_t)token * 64 + tid] = v;
    }

    const size_t base = (size_t)token * (NE * ND);
    #pragma unroll 4
    for (int i = tid; i < NE * ND / 4; i += 256) {
        float4 v = sx4[i];
        __half2 h0 = __floats2half2_rn(v.x, v.y);
        __half2 h1 = __floats2half2_rn(v.z, v.w);
        uint2 uh;
        uh.x = *reinterpret_cast<uint32_t*>(&h0);
        uh.y = *reinterpret_cast<uint32_t*>(&h1);
        *reinterpret_cast<uint2*>(g_Xh + base + (size_t)i * 4) = uh;
    }
}

__global__ __launch_bounds__(256) void prep_weight_kernel(
    const float* __restrict__ Wn, const float* __restrict__ bn,
    const float* __restrict__ Ws, const float* __restrict__ bs)
{
    const int idx = blockIdx.x * 256 + threadIdx.x;
    if (idx < ND * ND) {
        g_Wnh[idx] = __float2half_rn(Wn[idx]);
        g_Wsh[idx] = __float2half_rn(Ws[idx]);
    }
    if (idx < ND) g_bias[idx] = bn[idx] + bs[idx];
}

// ---------------------------------------------------------------------------
// fp16 HMMA GEMM (R11 config: 128x64 tile, 2 CTA/SM).
// R14/R15 deltas vs R11: packed-B ldmatrix.x4; one barrier per K-chunk.
// ---------------------------------------------------------------------------
#define BKC      64                       // k per chunk
#define NCHUNKS  (ND / BKC)               // 8
#define APAD_B   144                      // row stride bytes (128B data + 16 pad)
#define A_BYTES  (128 * APAD_B)           // 18432
#define W_BYTES  (64 * APAD_B)            // 9216
#define STG_B    (A_BYTES + 2 * W_BYTES)  // 36864
#define SM_STAGE 4352                     // after sbias(256) + ssmat(4096)
#define SMEM_TOTAL (SM_STAGE + 2 * STG_B) // 78080  (x2 CTAs = 156 KB < 227)
#define EPS_STRIDE 66

__global__ __launch_bounds__(256, 2) void gemm_hmma_kernel(float* __restrict__ out)
{
    extern __shared__ char sm[];
    const int tid = threadIdx.x;
    const int wid = tid >> 5, lane = tid & 31;
    const int warpM = wid & 3, warpN = wid >> 2;      // 4 x 2 warp grid

    const int ntile = blockIdx.x;        // 0..7  (fast: siblings share A rows in L2)
    const int mtile = blockIdx.y;        // 0..1023
    const int colBase = ntile * 64;
    const int rowBase = mtile * 128;
    const int tokBase = mtile * 16;

    float* sbias = reinterpret_cast<float*>(sm);
    float* ssmat = reinterpret_cast<float*>(sm + 256);
    if (tid < 64) sbias[tid] = g_bias[colBase + tid];
    for (int i = tid; i < 1024; i += 256) ssmat[i] = g_S[(size_t)tokBase * 64 + i];

    const uint32_t stage0 = smem_u32(sm) + SM_STAGE;
    const __half* Ah = g_Xh  + (size_t)rowBase * ND;
    const __half* Bn = g_Wnh + (size_t)colBase * ND;
    const __half* Bs = g_Wsh + (size_t)colBase * ND;

    // ---- async chunk loader: 8 x 16B per thread per chunk ----
    auto issue_chunk = [&](int c) {
        const uint32_t sb = stage0 + (c & 1) * STG_B;
        const int koff = c * BKC;
        #pragma unroll
        for (int i = 0; i < 4; i++) {                 // A: 1024 cp16
            const int q = tid + i * 256;
            const int row = q >> 3, seg = q & 7;
            cp16(sb + row * APAD_B + seg * 16,
                 Ah + (size_t)row * ND + koff + seg * 8);
        }
        #pragma unroll
        for (int i = 0; i < 2; i++) {                 // Wn, Ws: 512 cp16 each
            const int q = tid + i * 256;
            const int row = q >> 3, seg = q & 7;
            const uint32_t d = row * APAD_B + seg * 16;
            const size_t g = (size_t)row * ND + koff + seg * 8;
            cp16(sb + A_BYTES + d,           Bn + g);
            cp16(sb + A_BYTES + W_BYTES + d, Bs + g);
        }
    };

    float accP[2][4][4], accS[2][4][4];
    #pragma unroll
    for (int mt = 0; mt < 2; mt++)
        #pragma unroll
        for (int nt = 0; nt < 4; nt++)
            #pragma unroll
            for (int u = 0; u < 4; u++) { accP[mt][nt][u] = 0.f; accS[mt][nt][u] = 0.f; }

    issue_chunk(0);
    asm volatile("cp.async.commit_group;" ::: "memory");

    // ---- ldmatrix lane addressing ----
    // A (x4, one 16x16 m-tile): lanes 0-15 rows, 16-31 rows col+8
    const int a_row = ((lane >> 3) & 1) * 8 + (lane & 7);
    const int a_col = (lane >> 4) * 8;
    // B packed x4: matrix m = lane>>3 covers (n8-tile m>>1, k-half m&1)
    const int bm = lane >> 3, br = lane & 7;
    const uint32_t b_lane_off =
        (uint32_t)((warpN * 32 + (bm >> 1) * 8 + br) * APAD_B + (bm & 1) * 16);

    #pragma unroll 1
    for (int c = 0; c < NCHUNKS; c++) {
        asm volatile("cp.async.wait_group 0;" ::: "memory");
        __syncthreads();                  // single barrier per chunk:
        if (c + 1 < NCHUNKS) {            // buffer (c+1)&1's last compute was in
            issue_chunk(c + 1);           // iteration c-1, before this barrier
            asm volatile("cp.async.commit_group;" ::: "memory");
        }

        const uint32_t sb = stage0 + (c & 1) * STG_B;
        #pragma unroll
        for (int ks = 0; ks < 4; ks++) {
            const int k0 = ks * 16;
            uint32_t af[2][4];
            #pragma unroll
            for (int mt = 0; mt < 2; mt++) {
                const uint32_t ra = sb +
                    (warpM * 32 + mt * 16 + a_row) * APAD_B + (k0 + a_col) * 2;
                ldm_x4(af[mt], ra);
            }
            #pragma unroll
            for (int ntp = 0; ntp < 2; ntp++) {       // pair of n8 tiles per x4
                const uint32_t bo = sb + A_BYTES + b_lane_off +
                    (uint32_t)(ntp * 16 * APAD_B) + k0 * 2;
                uint32_t bn4[4], bs4[4];
                ldm_x4(bn4, bo);
                ldm_x4(bs4, bo + W_BYTES);
                #pragma unroll
                for (int sub = 0; sub < 2; sub++) {
                    const int nt = ntp * 2 + sub;
                    #pragma unroll
                    for (int mt = 0; mt < 2; mt++) {
                        mma16816(accP[mt][nt], af[mt], &bn4[sub * 2]);
                        mma16816(accS[mt][nt], af[mt], &bs4[sub * 2]);
                    }
                }
            }
        }
    }

    // ---- epilogue: acc -> smem (P, S full tiles), then mix + gelu + store --
    __syncthreads();                      // mainloop done before smem reuse
    float* sP = reinterpret_cast<float*>(sm + SM_STAGE);
    float* sS = sP + 128 * EPS_STRIDE;
    {
        const int rr = lane >> 2;
        const int cc = 2 * (lane & 3);
        #pragma unroll
        for (int mt = 0; mt < 2; mt++) {
            #pragma unroll
            for (int nt = 0; nt < 4; nt++) {
                const int r0 = warpM * 32 + mt * 16 + rr;
                const int c0 = warpN * 32 + nt * 8 + cc;
                sP[r0 * EPS_STRIDE + c0]       = accP[mt][nt][0];
                sP[r0 * EPS_STRIDE + c0 + 1]   = accP[mt][nt][1];
                sP[(r0 + 8) * EPS_STRIDE + c0]     = accP[mt][nt][2];
                sP[(r0 + 8) * EPS_STRIDE + c0 + 1] = accP[mt][nt][3];
                sS[r0 * EPS_STRIDE + c0]       = accS[mt][nt][0];
                sS[r0 * EPS_STRIDE + c0 + 1]   = accS[mt][nt][1];
                sS[(r0 + 8) * EPS_STRIDE + c0]     = accS[mt][nt][2];
                sS[(r0 + 8) * EPS_STRIDE + c0 + 1] = accS[mt][nt][3];
            }
        }
    }
    __syncthreads();

    {
        const int r = tid >> 1;              // local row 0..127
        const int cg = (tid & 1) * 32;       // col half
        const int tt = r >> 3, ei = r & 7;
        float sreg[8];
        #pragma unroll
        for (int j = 0; j < 8; j++) sreg[j] = ssmat[tt * 64 + ei * 8 + j];

        float* outrow = out + (size_t)(rowBase + r) * ND + colBase + cg;
        #pragma unroll
        for (int q = 0; q < 8; q++) {        // 8 x float4
            float4 o;
            #pragma unroll
            for (int u = 0; u < 4; u++) {
                const int cc = cg + q * 4 + u;
                float mix = 0.f;
                #pragma unroll
                for (int j = 0; j < 8; j++)
                    mix = fmaf(sreg[j], sP[(tt * 8 + j) * EPS_STRIDE + cc], mix);
                const float val = mix + sS[r * EPS_STRIDE + cc] + sbias[cc];
                (&o.x)[u] = gelu_exact(val);
            }
            *reinterpret_cast<float4*>(outrow + q * 4) = o;
        }
    }
}

// ---------------------------------------------------------------------------
extern "C" void kernel_launch(void* const* d_in, const int* in_sizes, int n_in,
                              void* d_out, int out_size)
{
    const float* x     = (const float*)d_in[0];
    const float* Wn    = (const float*)d_in[1];
    const float* bn    = (const float*)d_in[2];
    const float* Ws    = (const float*)d_in[3];
    const float* bs    = (const float*)d_in[4];
    const float* w_msg = (const float*)d_in[5];
    const float* b_msg = (const float*)d_in[6];
    const float* adjL  = (const float*)d_in[7];
    float* out = (float*)d_out;

    static bool attr_done = false;
    if (!attr_done) {
        cudaFuncSetAttribute(gemm_hmma_kernel,
                             cudaFuncAttributeMaxDynamicSharedMemorySize, SMEM_TOTAL);
        attr_done = true;
    }

    prep_token_kernel<<<NTOK, 256>>>(x, w_msg, b_msg, adjL);
    prep_weight_kernel<<<(ND * ND + 255) / 256, 256>>>(Wn, bn, Ws, bs);

    dim3 grid(ND / 64, NROWS / 128);     // (8, 1024)
    gemm_hmma_kernel<<<grid, 256, SMEM_TOTAL>>>(out);
}